// round 7
// baseline (speedup 1.0000x reference)
#include <cuda_runtime.h>
#include <cuda_bf16.h>
#include <math.h>
#include <stdint.h>

// Problem constants
#define BATCH 1024
#define NN 50
#define SS 50
#define HH 64
#define VOCAB 200000
#define VOUT 199999   // V-1 output columns

// Scratch for session embeddings a[B,H]
__device__ float g_a[BATCH * HH];

__device__ __forceinline__ float sigmoidf_(float x) {
    return 1.0f / (1.0f + expf(-x));
}

// ===========================================================================
// Phase 1: per-session GGNN cell + attention readout -> g_a
// (reverted to the measured-fastest float2 variant: 2 CTAs/SM)
// ===========================================================================
#define SM1_FLOATS 25472

__global__ void __launch_bounds__(256, 2) session_kernel(
    const int* __restrict__ alias_inputs, const float* __restrict__ ain,
    const float* __restrict__ aou, const int* __restrict__ items,
    const int* __restrict__ mask, const float* __restrict__ emb,
    const float* __restrict__ einw, const float* __restrict__ einb,
    const float* __restrict__ eouw, const float* __restrict__ eoub,
    const float* __restrict__ biah, const float* __restrict__ boah,
    const float* __restrict__ igw, const float* __restrict__ igb,
    const float* __restrict__ hgw, const float* __restrict__ hgb,
    const float* __restrict__ fc1w, const float* __restrict__ fc1b,
    const float* __restrict__ fc2w, const float* __restrict__ fc2b,
    const float* __restrict__ fc3w)
{
    extern __shared__ float sm[];
    float* sh  = sm;
    float* sb1 = sm + 3200;
    float* sb2 = sm + 6400;
    float* sb3 = sm + 9600;
    float* sb4 = sm + 12800;
    float* sb5 = sm + 16000;
    float* sw  = sm + 19200;        // 6144 floats
    float* sq1 = sm + 25344;
    float* salpha = sm + 25408;
    __shared__ int s_last;

    const int b = blockIdx.x;
    const int tid = threadIdx.x;

    // Gather h = emb[items]; stage ein_w
    for (int e = tid; e < 4096; e += 256) sw[e] = einw[e];
    for (int e = tid; e < NN * HH; e += 256) {
        int n = e >> 6, c = e & 63;
        sh[e] = emb[(size_t)items[b * NN + n] * HH + c];
    }
    __syncthreads();

    // t1 = h @ ein_w + ein_b  (adjacent-col float2 microtile)
    for (int p = tid; p < NN * 32; p += 256) {
        int n = p >> 5, c2 = (p & 31) * 2;
        float2 acc = *(const float2*)&einb[c2];
        const float* hr = sh + n * 64;
        #pragma unroll 8
        for (int k = 0; k < 64; k++) {
            float hv = hr[k];
            float2 w = *(const float2*)&sw[k * 64 + c2];
            acc.x += hv * w.x; acc.y += hv * w.y;
        }
        *(float2*)&sb1[n * 64 + c2] = acc;
    }
    __syncthreads();
    // stage eou_w, compute t2
    for (int e = tid; e < 4096; e += 256) sw[e] = eouw[e];
    __syncthreads();
    for (int p = tid; p < NN * 32; p += 256) {
        int n = p >> 5, c2 = (p & 31) * 2;
        float2 acc = *(const float2*)&eoub[c2];
        const float* hr = sh + n * 64;
        #pragma unroll 8
        for (int k = 0; k < 64; k++) {
            float hv = hr[k];
            float2 w = *(const float2*)&sw[k * 64 + c2];
            acc.x += hv * w.x; acc.y += hv * w.y;
        }
        *(float2*)&sb2[n * 64 + c2] = acc;
    }
    __syncthreads();

    // input_in = ain @ t1 + b_iah -> sb3 ; input_out = aou @ t2 + b_oah -> sb4
    for (int p = tid; p < NN * 32; p += 256) {
        int n = p >> 5, c2 = (p & 31) * 2;
        float2 a1 = *(const float2*)&biah[c2];
        float2 a2 = *(const float2*)&boah[c2];
        const float* ar = ain + (size_t)b * (NN * NN) + n * NN;
        const float* br = aou + (size_t)b * (NN * NN) + n * NN;
        #pragma unroll 5
        for (int j = 0; j < NN; j++) {
            float av = ar[j], bv = br[j];
            float2 t1 = *(const float2*)&sb1[j * 64 + c2];
            float2 t2 = *(const float2*)&sb2[j * 64 + c2];
            a1.x += av * t1.x; a1.y += av * t1.y;
            a2.x += bv * t2.x; a2.y += bv * t2.y;
        }
        *(float2*)&sb3[n * 64 + c2] = a1;
        *(float2*)&sb4[n * 64 + c2] = a2;
    }
    __syncthreads();

    // GRU gates: 3 gates x 2 half-col chunks of 32 cols
    for (int g = 0; g < 3; g++) {
        for (int hf = 0; hf < 2; hf++) {
            int gcol = g * 64 + hf * 32;
            for (int e = tid; e < 4096; e += 256) {
                int k = e >> 5, cc = e & 31;
                sw[e] = igw[k * 192 + gcol + cc];
            }
            for (int e = tid; e < 2048; e += 256) {
                int k = e >> 5, cc = e & 31;
                sw[4096 + e] = hgw[k * 192 + gcol + cc];
            }
            __syncthreads();

            for (int p = tid; p < NN * 16; p += 256) {
                int n = p >> 4, cc2 = (p & 15) * 2;
                float2 si = *(const float2*)&igb[gcol + cc2];
                float2 shc = *(const float2*)&hgb[gcol + cc2];
                const float* r3 = sb3 + n * 64;
                const float* r4 = sb4 + n * 64;
                const float* hr = sh + n * 64;
                #pragma unroll 8
                for (int k = 0; k < 64; k++) {
                    float v3 = r3[k], v4 = r4[k], vh = hr[k];
                    float2 w1 = *(const float2*)&sw[k * 32 + cc2];
                    float2 w2 = *(const float2*)&sw[(64 + k) * 32 + cc2];
                    float2 wh = *(const float2*)&sw[4096 + k * 32 + cc2];
                    si.x += v3 * w1.x + v4 * w2.x;
                    si.y += v3 * w1.y + v4 * w2.y;
                    shc.x += vh * wh.x;
                    shc.y += vh * wh.y;
                }
                int e0 = n * 64 + hf * 32 + cc2;
                if (g == 0) {
                    sb1[e0]     = sigmoidf_(si.x + shc.x);
                    sb1[e0 + 1] = sigmoidf_(si.y + shc.y);
                } else if (g == 1) {
                    sb2[e0]     = sigmoidf_(si.x + shc.x);
                    sb2[e0 + 1] = sigmoidf_(si.y + shc.y);
                } else {
                    float ng0 = tanhf(si.x + sb1[e0] * shc.x);
                    float ng1 = tanhf(si.y + sb1[e0 + 1] * shc.y);
                    sb5[e0]     = ng0 + sb2[e0] * (sh[e0] - ng0);
                    sb5[e0 + 1] = ng1 + sb2[e0 + 1] * (sh[e0 + 1] - ng1);
                }
            }
            __syncthreads();
        }
    }

    // ---- attention readout, h_final = sb5 ----
    if (tid == 0) {
        int m = 0;
        for (int s = 0; s < SS; s++) m += mask[b * SS + s];
        s_last = m - 1;
    }
    for (int e = tid; e < SS * HH; e += 256) {
        int s = e >> 6, c = e & 63;
        sb3[e] = sb5[alias_inputs[b * SS + s] * 64 + c];
    }
    for (int e = tid; e < 4096; e += 256) sw[e] = fc2w[e];
    __syncthreads();

    if (tid < 64) {
        int c = tid;
        float q = fc1b[c];
        const float* htr = sb3 + s_last * 64;
        #pragma unroll 8
        for (int k = 0; k < 64; k++) q += htr[k] * fc1w[k * 64 + c];
        sq1[c] = q;
    }
    __syncthreads();

    for (int p = tid; p < SS * 32; p += 256) {
        int s = p >> 5, c2 = (p & 31) * 2;
        float2 q = *(const float2*)&fc2b[c2];
        const float* sr = sb3 + s * 64;
        #pragma unroll 8
        for (int k = 0; k < 64; k++) {
            float sv = sr[k];
            float2 w = *(const float2*)&sw[k * 64 + c2];
            q.x += sv * w.x; q.y += sv * w.y;
        }
        int e0 = s * 64 + c2;
        sb4[e0]     = sigmoidf_(sq1[c2] + q.x) * fc3w[c2];
        sb4[e0 + 1] = sigmoidf_(sq1[c2 + 1] + q.y) * fc3w[c2 + 1];
    }
    __syncthreads();

    if (tid < SS) {
        float al = 0.0f;
        #pragma unroll 8
        for (int c = 0; c < 64; c++) al += sb4[tid * 64 + c];
        salpha[tid] = al * (float)mask[b * SS + tid];
    }
    __syncthreads();

    if (tid < 64) {
        float a = 0.0f;
        #pragma unroll 5
        for (int s = 0; s < SS; s++) a += salpha[s] * sb3[s * 64 + tid];
        g_a[b * 64 + tid] = a;
    }
}

// ===========================================================================
// Phase 2: mma.sync bf16 split-precision GEMM, cp.async-pipelined,
// 512 threads / 16 warps (4x4), warp tile 32x32 -> occ 50% (2 CTA x 16 warps).
//   fp32 x = hi(trunc16) + lo;  out = Ahi*Ehi + Ahi*Elo + Alo*Ehi
// A staged once per CTA as bf16 hi/lo; E double-buffered fp32 via cp.async;
// B fragments split hi/lo in registers. T_VTILES v-tiles per CTA.
// ===========================================================================

#define EPITCH 72                       // A bf16 row pitch (elems)
#define EP 68                           // E fp32 row pitch (floats)
#define OFF_AHI 0
#define OFF_ALO 18432                   // 128*72*2
#define OFF_E0  36864
#define OFF_E1  71680                   // +128*68*4
#define GT_BYTES 106496
#define T_VTILES 8
#define NVTILES 1563                    // ceil(VOUT/128)

static __device__ __forceinline__ uint32_t smem_u32(const void* p) {
    uint32_t a;
    asm("{ .reg .u64 t; cvta.to.shared.u64 t, %1; cvt.u32.u64 %0, t; }"
        : "=r"(a) : "l"(p));
    return a;
}

static __device__ __forceinline__ void ldsm_x4(
    uint32_t& r0, uint32_t& r1, uint32_t& r2, uint32_t& r3, uint32_t addr)
{
    asm volatile("ldmatrix.sync.aligned.m8n8.x4.shared.b16 {%0,%1,%2,%3}, [%4];"
                 : "=r"(r0), "=r"(r1), "=r"(r2), "=r"(r3) : "r"(addr));
}

static __device__ __forceinline__ void mma_bf16(
    float* c, const uint32_t* a, const uint32_t* b)
{
    asm volatile(
        "mma.sync.aligned.m16n8k16.row.col.f32.bf16.bf16.f32 "
        "{%0,%1,%2,%3}, {%4,%5,%6,%7}, {%8,%9}, {%0,%1,%2,%3};"
        : "+f"(c[0]), "+f"(c[1]), "+f"(c[2]), "+f"(c[3])
        : "r"(a[0]), "r"(a[1]), "r"(a[2]), "r"(a[3]), "r"(b[0]), "r"(b[1]));
}

// hi = truncate-to-bf16 pair pack; lo = exact residual, RN to bf16 pair
static __device__ __forceinline__ uint32_t hi_pack(float x, float y) {
    return __byte_perm(__float_as_uint(x), __float_as_uint(y), 0x7632);
}
static __device__ __forceinline__ float lo_res(float x) {
    return x - __uint_as_float(__float_as_uint(x) & 0xFFFF0000u);
}
static __device__ __forceinline__ uint32_t lo_pack(float x, float y) {
    uint32_t r;
    asm("cvt.rn.bf16x2.f32 %0, %1, %2;" : "=r"(r)
        : "f"(lo_res(y)), "f"(lo_res(x)));   // low16 = cvt(x)
    return r;
}

#define CP_ASYNC16(dst, src) \
    asm volatile("cp.async.cg.shared.global [%0], [%1], 16;" \
                 :: "r"(dst), "l"(src))
#define CP_COMMIT()  asm volatile("cp.async.commit_group;" ::: "memory")
#define CP_WAIT(N)   asm volatile("cp.async.wait_group %0;" :: "n"(N) : "memory")

__global__ void __launch_bounds__(512, 2) gemm_mma_kernel(
    const float* __restrict__ emb, float* __restrict__ out)
{
    extern __shared__ char smc[];
    const uint32_t smb = smem_u32(smc);
    const int tid = threadIdx.x;
    const int wid = tid >> 5;
    const int lid = tid & 31;
    const int warp_m = wid & 3;        // 0..3 -> 32-row block
    const int warp_n = wid >> 2;       // 0..3 -> 32-col block
    const int b0 = blockIdx.x * 128;   // batch tile (fast dim -> emb L2 reuse)
    const int vt0 = blockIdx.y * T_VTILES;
    const int nv = (NVTILES - vt0 < T_VTILES) ? (NVTILES - vt0) : T_VTILES;

    __nv_bfloat16* saHi = (__nv_bfloat16*)(smc + OFF_AHI);
    __nv_bfloat16* saLo = (__nv_bfloat16*)(smc + OFF_ALO);

    // ---- Stage A tile once: a[b0+m][k] -> hi/lo bf16 (truncation split)
    for (int idx = tid; idx < 128 * 16; idx += 512) {
        int m = idx >> 4, q = idx & 15;
        float4 v = *(const float4*)&g_a[(b0 + m) * 64 + q * 4];
        int o = m * EPITCH + q * 4;
        *(uint32_t*)&saHi[o]     = hi_pack(v.x, v.y);
        *(uint32_t*)&saHi[o + 2] = hi_pack(v.z, v.w);
        *(uint32_t*)&saLo[o]     = lo_pack(v.x, v.y);
        *(uint32_t*)&saLo[o + 2] = lo_pack(v.z, v.w);
    }

    // ---- Prefetch E tile 0 (fp32, cp.async)
    {
        uint32_t dstb = smb + OFF_E0;
        #pragma unroll
        for (int i = 0; i < 4; i++) {
            int idx = tid + i * 512;
            int row = idx >> 4, c = (idx & 15) * 4;
            int grow = vt0 * 128 + row;
            if (grow < VOUT)
                CP_ASYNC16(dstb + (row * EP + c) * 4,
                           emb + (size_t)(1 + grow) * 64 + c);
        }
        CP_COMMIT();
    }

    // ldmatrix lane address components (A)
    const int a_row = (lid & 7) + ((lid >> 3) & 1) * 8;
    const int a_kc  = ((lid >> 4) & 1) * 8;
    const uint32_t aHiB = smb + OFF_AHI
        + ((warp_m * 32 + a_row) * EPITCH + a_kc) * 2;
    const uint32_t aLoB = smb + OFF_ALO
        + ((warp_m * 32 + a_row) * EPITCH + a_kc) * 2;

    // E per-thread fragment offset pieces
    const int e_r = lid >> 2;          // row within 8-row group
    const int e_q = (lid & 3) * 2;     // k pair offset

    for (int t = 0; t < nv; t++) {
        int vt = vt0 + t;
        if (t + 1 < nv) {
            uint32_t dstb = smb + (((t + 1) & 1) ? OFF_E1 : OFF_E0);
            #pragma unroll
            for (int i = 0; i < 4; i++) {
                int idx = tid + i * 512;
                int row = idx >> 4, c = (idx & 15) * 4;
                int grow = (vt + 1) * 128 + row;
                if (grow < VOUT)
                    CP_ASYNC16(dstb + (row * EP + c) * 4,
                               emb + (size_t)(1 + grow) * 64 + c);
            }
            CP_COMMIT();
            CP_WAIT(1);
        } else {
            CP_WAIT(0);
        }
        __syncthreads();

        const float* Ebuf = (const float*)(smc + ((t & 1) ? OFF_E1 : OFF_E0));

        float c[2][4][4];
        #pragma unroll
        for (int i = 0; i < 2; i++)
            #pragma unroll
            for (int j = 0; j < 4; j++)
                #pragma unroll
                for (int q = 0; q < 4; q++) c[i][j][q] = 0.0f;

        #pragma unroll
        for (int ks = 0; ks < 4; ks++) {
            uint32_t ah[2][4], al[2][4];
            #pragma unroll
            for (int mf = 0; mf < 2; mf++) {
                ldsm_x4(ah[mf][0], ah[mf][1], ah[mf][2], ah[mf][3],
                        aHiB + mf * 16 * EPITCH * 2 + ks * 32);
                ldsm_x4(al[mf][0], al[mf][1], al[mf][2], al[mf][3],
                        aLoB + mf * 16 * EPITCH * 2 + ks * 32);
            }
            #pragma unroll
            for (int nf = 0; nf < 4; nf++) {
                const float* ep = Ebuf
                    + (warp_n * 32 + nf * 8 + e_r) * EP + ks * 16 + e_q;
                float2 u0 = *(const float2*)ep;
                float2 u1 = *(const float2*)(ep + 8);
                uint32_t bh[2], bl[2];
                bh[0] = hi_pack(u0.x, u0.y);
                bh[1] = hi_pack(u1.x, u1.y);
                bl[0] = lo_pack(u0.x, u0.y);
                bl[1] = lo_pack(u1.x, u1.y);
                #pragma unroll
                for (int mf = 0; mf < 2; mf++) {
                    mma_bf16(c[mf][nf], ah[mf], bh);
                    mma_bf16(c[mf][nf], ah[mf], bl);
                    mma_bf16(c[mf][nf], al[mf], bh);
                }
            }
        }

        // ---- Epilogue: direct stores
        const int v0 = vt * 128;
        const int rbase = b0 + warp_m * 32 + (lid >> 2);
        const int cbase = v0 + warp_n * 32 + (lid & 3) * 2;
        #pragma unroll
        for (int mf = 0; mf < 2; mf++) {
            #pragma unroll
            for (int nf = 0; nf < 4; nf++) {
                int col = cbase + nf * 8;
                float* r0p = out + (size_t)(rbase + mf * 16) * VOUT;
                float* r1p = r0p + (size_t)8 * VOUT;
                if (col < VOUT) {
                    r0p[col] = c[mf][nf][0]; r1p[col] = c[mf][nf][2];
                }
                if (col + 1 < VOUT) {
                    r0p[col + 1] = c[mf][nf][1]; r1p[col + 1] = c[mf][nf][3];
                }
            }
        }
        __syncthreads();   // buffer t&1 free for prefetch of t+2
    }
}

// ===========================================================================
extern "C" void kernel_launch(void* const* d_in, const int* in_sizes, int n_in,
                              void* d_out, int out_size)
{
    const int*   alias_inputs = (const int*)  d_in[0];
    const float* ain   = (const float*)d_in[1];
    const float* aou   = (const float*)d_in[2];
    const int*   items = (const int*)  d_in[3];
    const int*   mask  = (const int*)  d_in[4];
    /* d_in[5] edge_index unused */
    const float* emb   = (const float*)d_in[6];
    const float* einw  = (const float*)d_in[7];
    const float* einb  = (const float*)d_in[8];
    const float* eouw  = (const float*)d_in[9];
    const float* eoub  = (const float*)d_in[10];
    const float* biah  = (const float*)d_in[11];
    const float* boah  = (const float*)d_in[12];
    const float* igw   = (const float*)d_in[13];
    const float* igb   = (const float*)d_in[14];
    const float* hgw   = (const float*)d_in[15];
    const float* hgb   = (const float*)d_in[16];
    const float* fc1w  = (const float*)d_in[17];
    const float* fc1b  = (const float*)d_in[18];
    const float* fc2w  = (const float*)d_in[19];
    const float* fc2b  = (const float*)d_in[20];
    const float* fc3w  = (const float*)d_in[21];
    float* out = (float*)d_out;

    cudaFuncSetAttribute(session_kernel,
                         cudaFuncAttributeMaxDynamicSharedMemorySize,
                         SM1_FLOATS * 4);
    cudaFuncSetAttribute(gemm_mma_kernel,
                         cudaFuncAttributeMaxDynamicSharedMemorySize,
                         GT_BYTES);

    session_kernel<<<BATCH, 256, SM1_FLOATS * 4>>>(
        alias_inputs, ain, aou, items, mask, emb,
        einw, einb, eouw, eoub, biah, boah,
        igw, igb, hgw, hgb, fc1w, fc1b, fc2w, fc2b, fc3w);

    dim3 grid(8, (NVTILES + T_VTILES - 1) / T_VTILES, 1);
    gemm_mma_kernel<<<grid, 512, GT_BYTES>>>(emb, out);
}

// round 8
// speedup vs baseline: 1.0584x; 1.0584x over previous
#include <cuda_runtime.h>
#include <cuda_bf16.h>
#include <math.h>
#include <stdint.h>

// Problem constants
#define BATCH 1024
#define NN 50
#define SS 50
#define HH 64
#define VOCAB 200000
#define VOUT 199999   // V-1 output columns

// Scratch: session embeddings + pre-split emb (bf16 hi/lo)
__device__ float g_a[BATCH * HH];
__device__ __nv_bfloat16 g_ehi[VOCAB * HH];
__device__ __nv_bfloat16 g_elo[VOCAB * HH];

__device__ __forceinline__ float sigmoidf_(float x) {
    return 1.0f / (1.0f + expf(-x));
}

// hi = truncate-to-bf16 pair pack; lo = exact residual, RN to bf16 pair
static __device__ __forceinline__ uint32_t hi_pack(float x, float y) {
    return __byte_perm(__float_as_uint(x), __float_as_uint(y), 0x7632);
}
static __device__ __forceinline__ float lo_res(float x) {
    return x - __uint_as_float(__float_as_uint(x) & 0xFFFF0000u);
}
static __device__ __forceinline__ uint32_t lo_pack(float x, float y) {
    uint32_t r;
    asm("cvt.rn.bf16x2.f32 %0, %1, %2;" : "=r"(r)
        : "f"(lo_res(y)), "f"(lo_res(x)));   // low16 = cvt(x)
    return r;
}

// ===========================================================================
// Phase 0: split emb fp32 -> bf16 hi/lo  (one float4 per thread)
// ===========================================================================
__global__ void __launch_bounds__(256) split_kernel(const float* __restrict__ emb)
{
    int idx = blockIdx.x * 256 + threadIdx.x;
    if (idx < VOCAB * (HH / 4)) {
        float4 v = ((const float4*)emb)[idx];
        uint2 h = make_uint2(hi_pack(v.x, v.y), hi_pack(v.z, v.w));
        uint2 l = make_uint2(lo_pack(v.x, v.y), lo_pack(v.z, v.w));
        ((uint2*)g_ehi)[idx] = h;
        ((uint2*)g_elo)[idx] = l;
    }
}

// ===========================================================================
// Phase 1: per-session GGNN cell + attention readout -> g_a
// (float2 variant, measured fastest: ~493us, 2 CTAs/SM)
// ===========================================================================
#define SM1_FLOATS 25472

__global__ void __launch_bounds__(256, 2) session_kernel(
    const int* __restrict__ alias_inputs, const float* __restrict__ ain,
    const float* __restrict__ aou, const int* __restrict__ items,
    const int* __restrict__ mask, const float* __restrict__ emb,
    const float* __restrict__ einw, const float* __restrict__ einb,
    const float* __restrict__ eouw, const float* __restrict__ eoub,
    const float* __restrict__ biah, const float* __restrict__ boah,
    const float* __restrict__ igw, const float* __restrict__ igb,
    const float* __restrict__ hgw, const float* __restrict__ hgb,
    const float* __restrict__ fc1w, const float* __restrict__ fc1b,
    const float* __restrict__ fc2w, const float* __restrict__ fc2b,
    const float* __restrict__ fc3w)
{
    extern __shared__ float sm[];
    float* sh  = sm;
    float* sb1 = sm + 3200;
    float* sb2 = sm + 6400;
    float* sb3 = sm + 9600;
    float* sb4 = sm + 12800;
    float* sb5 = sm + 16000;
    float* sw  = sm + 19200;        // 6144 floats
    float* sq1 = sm + 25344;
    float* salpha = sm + 25408;
    __shared__ int s_last;

    const int b = blockIdx.x;
    const int tid = threadIdx.x;

    for (int e = tid; e < 4096; e += 256) sw[e] = einw[e];
    for (int e = tid; e < NN * HH; e += 256) {
        int n = e >> 6, c = e & 63;
        sh[e] = emb[(size_t)items[b * NN + n] * HH + c];
    }
    __syncthreads();

    for (int p = tid; p < NN * 32; p += 256) {
        int n = p >> 5, c2 = (p & 31) * 2;
        float2 acc = *(const float2*)&einb[c2];
        const float* hr = sh + n * 64;
        #pragma unroll 8
        for (int k = 0; k < 64; k++) {
            float hv = hr[k];
            float2 w = *(const float2*)&sw[k * 64 + c2];
            acc.x += hv * w.x; acc.y += hv * w.y;
        }
        *(float2*)&sb1[n * 64 + c2] = acc;
    }
    __syncthreads();
    for (int e = tid; e < 4096; e += 256) sw[e] = eouw[e];
    __syncthreads();
    for (int p = tid; p < NN * 32; p += 256) {
        int n = p >> 5, c2 = (p & 31) * 2;
        float2 acc = *(const float2*)&eoub[c2];
        const float* hr = sh + n * 64;
        #pragma unroll 8
        for (int k = 0; k < 64; k++) {
            float hv = hr[k];
            float2 w = *(const float2*)&sw[k * 64 + c2];
            acc.x += hv * w.x; acc.y += hv * w.y;
        }
        *(float2*)&sb2[n * 64 + c2] = acc;
    }
    __syncthreads();

    for (int p = tid; p < NN * 32; p += 256) {
        int n = p >> 5, c2 = (p & 31) * 2;
        float2 a1 = *(const float2*)&biah[c2];
        float2 a2 = *(const float2*)&boah[c2];
        const float* ar = ain + (size_t)b * (NN * NN) + n * NN;
        const float* br = aou + (size_t)b * (NN * NN) + n * NN;
        #pragma unroll 5
        for (int j = 0; j < NN; j++) {
            float av = ar[j], bv = br[j];
            float2 t1 = *(const float2*)&sb1[j * 64 + c2];
            float2 t2 = *(const float2*)&sb2[j * 64 + c2];
            a1.x += av * t1.x; a1.y += av * t1.y;
            a2.x += bv * t2.x; a2.y += bv * t2.y;
        }
        *(float2*)&sb3[n * 64 + c2] = a1;
        *(float2*)&sb4[n * 64 + c2] = a2;
    }
    __syncthreads();

    for (int g = 0; g < 3; g++) {
        for (int hf = 0; hf < 2; hf++) {
            int gcol = g * 64 + hf * 32;
            for (int e = tid; e < 4096; e += 256) {
                int k = e >> 5, cc = e & 31;
                sw[e] = igw[k * 192 + gcol + cc];
            }
            for (int e = tid; e < 2048; e += 256) {
                int k = e >> 5, cc = e & 31;
                sw[4096 + e] = hgw[k * 192 + gcol + cc];
            }
            __syncthreads();

            for (int p = tid; p < NN * 16; p += 256) {
                int n = p >> 4, cc2 = (p & 15) * 2;
                float2 si = *(const float2*)&igb[gcol + cc2];
                float2 shc = *(const float2*)&hgb[gcol + cc2];
                const float* r3 = sb3 + n * 64;
                const float* r4 = sb4 + n * 64;
                const float* hr = sh + n * 64;
                #pragma unroll 8
                for (int k = 0; k < 64; k++) {
                    float v3 = r3[k], v4 = r4[k], vh = hr[k];
                    float2 w1 = *(const float2*)&sw[k * 32 + cc2];
                    float2 w2 = *(const float2*)&sw[(64 + k) * 32 + cc2];
                    float2 wh = *(const float2*)&sw[4096 + k * 32 + cc2];
                    si.x += v3 * w1.x + v4 * w2.x;
                    si.y += v3 * w1.y + v4 * w2.y;
                    shc.x += vh * wh.x;
                    shc.y += vh * wh.y;
                }
                int e0 = n * 64 + hf * 32 + cc2;
                if (g == 0) {
                    sb1[e0]     = sigmoidf_(si.x + shc.x);
                    sb1[e0 + 1] = sigmoidf_(si.y + shc.y);
                } else if (g == 1) {
                    sb2[e0]     = sigmoidf_(si.x + shc.x);
                    sb2[e0 + 1] = sigmoidf_(si.y + shc.y);
                } else {
                    float ng0 = tanhf(si.x + sb1[e0] * shc.x);
                    float ng1 = tanhf(si.y + sb1[e0 + 1] * shc.y);
                    sb5[e0]     = ng0 + sb2[e0] * (sh[e0] - ng0);
                    sb5[e0 + 1] = ng1 + sb2[e0 + 1] * (sh[e0 + 1] - ng1);
                }
            }
            __syncthreads();
        }
    }

    if (tid == 0) {
        int m = 0;
        for (int s = 0; s < SS; s++) m += mask[b * SS + s];
        s_last = m - 1;
    }
    for (int e = tid; e < SS * HH; e += 256) {
        int s = e >> 6, c = e & 63;
        sb3[e] = sb5[alias_inputs[b * SS + s] * 64 + c];
    }
    for (int e = tid; e < 4096; e += 256) sw[e] = fc2w[e];
    __syncthreads();

    if (tid < 64) {
        int c = tid;
        float q = fc1b[c];
        const float* htr = sb3 + s_last * 64;
        #pragma unroll 8
        for (int k = 0; k < 64; k++) q += htr[k] * fc1w[k * 64 + c];
        sq1[c] = q;
    }
    __syncthreads();

    for (int p = tid; p < SS * 32; p += 256) {
        int s = p >> 5, c2 = (p & 31) * 2;
        float2 q = *(const float2*)&fc2b[c2];
        const float* sr = sb3 + s * 64;
        #pragma unroll 8
        for (int k = 0; k < 64; k++) {
            float sv = sr[k];
            float2 w = *(const float2*)&sw[k * 64 + c2];
            q.x += sv * w.x; q.y += sv * w.y;
        }
        int e0 = s * 64 + c2;
        sb4[e0]     = sigmoidf_(sq1[c2] + q.x) * fc3w[c2];
        sb4[e0 + 1] = sigmoidf_(sq1[c2 + 1] + q.y) * fc3w[c2 + 1];
    }
    __syncthreads();

    if (tid < SS) {
        float al = 0.0f;
        #pragma unroll 8
        for (int c = 0; c < 64; c++) al += sb4[tid * 64 + c];
        salpha[tid] = al * (float)mask[b * SS + tid];
    }
    __syncthreads();

    if (tid < 64) {
        float a = 0.0f;
        #pragma unroll 5
        for (int s = 0; s < SS; s++) a += salpha[s] * sb3[s * 64 + tid];
        g_a[b * 64 + tid] = a;
    }
}

// ===========================================================================
// Phase 2: mma.sync bf16 split GEMM, all-ldmatrix mainloop.
// E pre-split to bf16 hi/lo in global (prepass); tiles cp.async'd into
// XOR-swizzled smem (128B rows, no padding, conflict-free ldsm).
// 256 thr / 8 warps (2m x 4n), warp tile 64x32, double-buffered E,
// T_VTILES v-tiles per CTA.  out = Ahi*Ehi + Ahi*Elo + Alo*Ehi.
// ===========================================================================

// smem byte offsets (rows of 128B, swizzled chunk16: c ^= (row & 7))
#define OFF_AHI 0
#define OFF_ALO 16384
#define OFF_E0H 32768
#define OFF_E0L 49152
#define OFF_E1H 65536
#define OFF_E1L 81920
#define GT_BYTES 98304
#define T_VTILES 8
#define NVTILES 1563                    // ceil(VOUT/128)

static __device__ __forceinline__ uint32_t smem_u32(const void* p) {
    uint32_t a;
    asm("{ .reg .u64 t; cvta.to.shared.u64 t, %1; cvt.u32.u64 %0, t; }"
        : "=r"(a) : "l"(p));
    return a;
}

// swizzled byte address of 16B chunk c in row r (row pitch 128B)
static __device__ __forceinline__ uint32_t sw_addr(int r, int c) {
    return (uint32_t)(r * 128 + ((c ^ (r & 7)) << 4));
}

static __device__ __forceinline__ void ldsm_x4(
    uint32_t& r0, uint32_t& r1, uint32_t& r2, uint32_t& r3, uint32_t addr)
{
    asm volatile("ldmatrix.sync.aligned.m8n8.x4.shared.b16 {%0,%1,%2,%3}, [%4];"
                 : "=r"(r0), "=r"(r1), "=r"(r2), "=r"(r3) : "r"(addr));
}

static __device__ __forceinline__ void mma_bf16(
    float* c, const uint32_t* a, const uint32_t* b)
{
    asm volatile(
        "mma.sync.aligned.m16n8k16.row.col.f32.bf16.bf16.f32 "
        "{%0,%1,%2,%3}, {%4,%5,%6,%7}, {%8,%9}, {%0,%1,%2,%3};"
        : "+f"(c[0]), "+f"(c[1]), "+f"(c[2]), "+f"(c[3])
        : "r"(a[0]), "r"(a[1]), "r"(a[2]), "r"(a[3]), "r"(b[0]), "r"(b[1]));
}

#define CP_ASYNC16(dst, src) \
    asm volatile("cp.async.cg.shared.global [%0], [%1], 16;" \
                 :: "r"(dst), "l"(src))
#define CP_COMMIT()  asm volatile("cp.async.commit_group;" ::: "memory")
#define CP_WAIT(N)   asm volatile("cp.async.wait_group %0;" :: "n"(N) : "memory")

// prefetch one E tile (hi+lo, 128 rows x 64 bf16) into swizzled smem
static __device__ __forceinline__ void prefetch_e(
    uint32_t smb, uint32_t offH, uint32_t offL, int vt, int tid)
{
    #pragma unroll
    for (int i = 0; i < 4; i++) {
        int idx = tid + i * 256;
        int r = idx >> 3, c = idx & 7;          // 16B chunk c of row r
        int grow = vt * 128 + r;
        if (grow < VOUT) {
            const char* sh = (const char*)g_ehi
                + ((size_t)(1 + grow) * 64 + c * 8) * 2;
            const char* sl = (const char*)g_elo
                + ((size_t)(1 + grow) * 64 + c * 8) * 2;
            uint32_t sa = sw_addr(r, c);
            CP_ASYNC16(smb + offH + sa, sh);
            CP_ASYNC16(smb + offL + sa, sl);
        }
    }
    CP_COMMIT();
}

__global__ void __launch_bounds__(256, 2) gemm_mma_kernel(
    float* __restrict__ out)
{
    extern __shared__ char smc[];
    const uint32_t smb = smem_u32(smc);
    const int tid = threadIdx.x;
    const int wid = tid >> 5;
    const int lid = tid & 31;
    const int warp_m = wid & 1;        // 0..1 -> 64-row block
    const int warp_n = wid >> 1;       // 0..3 -> 32-col block
    const int b0 = blockIdx.x * 128;   // batch tile (fast dim -> emb L2 reuse)
    const int vt0 = blockIdx.y * T_VTILES;
    const int nv = (NVTILES - vt0 < T_VTILES) ? (NVTILES - vt0) : T_VTILES;

    // ---- Stage A tile once: a[b0+m][k] -> hi/lo bf16 swizzled
    for (int idx = tid; idx < 128 * 16; idx += 256) {
        int m = idx >> 4, q = idx & 15;         // 4-elem group q
        float4 v = *(const float4*)&g_a[(b0 + m) * 64 + q * 4];
        uint32_t a = sw_addr(m, q >> 1) + (q & 1) * 8;
        *(uint2*)(smc + OFF_AHI + a) =
            make_uint2(hi_pack(v.x, v.y), hi_pack(v.z, v.w));
        *(uint2*)(smc + OFF_ALO + a) =
            make_uint2(lo_pack(v.x, v.y), lo_pack(v.z, v.w));
    }

    prefetch_e(smb, OFF_E0H, OFF_E0L, vt0, tid);

    // ldmatrix lane address components
    // A (x4): lanes 0-7 rows0-7 k0 | 8-15 rows8-15 k0 | 16-23 rows0-7 k8 | 24-31 rows8-15 k8
    const int a_row = (lid & 7) + ((lid >> 3) & 1) * 8;
    const int a_c8  = (lid >> 4) & 1;          // chunk offset within kstep
    // B (x4): lanes 0-7 n0-7 k0 | 8-15 n0-7 k8 | 16-23 n8-15 k0 | 24-31 n8-15 k8
    const int b_row = (lid & 7) + ((lid >> 4) & 1) * 8;
    const int b_c8  = (lid >> 3) & 1;

    for (int t = 0; t < nv; t++) {
        int vt = vt0 + t;
        if (t + 1 < nv) {
            if ((t + 1) & 1) prefetch_e(smb, OFF_E1H, OFF_E1L, vt + 1, tid);
            else             prefetch_e(smb, OFF_E0H, OFF_E0L, vt + 1, tid);
            CP_WAIT(1);
        } else {
            CP_WAIT(0);
        }
        __syncthreads();

        const uint32_t eH = smb + ((t & 1) ? OFF_E1H : OFF_E0H);
        const uint32_t eL = smb + ((t & 1) ? OFF_E1L : OFF_E0L);

        float c[4][4][4];
        #pragma unroll
        for (int i = 0; i < 4; i++)
            #pragma unroll
            for (int j = 0; j < 4; j++)
                #pragma unroll
                for (int q = 0; q < 4; q++) c[i][j][q] = 0.0f;

        #pragma unroll
        for (int ks = 0; ks < 4; ks++) {
            uint32_t ah[4][4], al[4][4];
            #pragma unroll
            for (int mf = 0; mf < 4; mf++) {
                int rm = warp_m * 64 + mf * 16 + a_row;
                uint32_t sa = sw_addr(rm, ks * 2 + a_c8);
                ldsm_x4(ah[mf][0], ah[mf][1], ah[mf][2], ah[mf][3],
                        smb + OFF_AHI + sa);
                ldsm_x4(al[mf][0], al[mf][1], al[mf][2], al[mf][3],
                        smb + OFF_ALO + sa);
            }
            #pragma unroll
            for (int np = 0; np < 2; np++) {
                int rn = warp_n * 32 + np * 16 + b_row;
                uint32_t sa = sw_addr(rn, ks * 2 + b_c8);
                uint32_t bh[4], bl[4];
                ldsm_x4(bh[0], bh[1], bh[2], bh[3], eH + sa);
                ldsm_x4(bl[0], bl[1], bl[2], bl[3], eL + sa);
                #pragma unroll
                for (int h = 0; h < 2; h++) {
                    int nf = np * 2 + h;
                    #pragma unroll
                    for (int mf = 0; mf < 4; mf++) {
                        mma_bf16(c[mf][nf], ah[mf], bh + 2 * h);
                        mma_bf16(c[mf][nf], ah[mf], bl + 2 * h);
                        mma_bf16(c[mf][nf], al[mf], bh + 2 * h);
                    }
                }
            }
        }

        // ---- Epilogue: direct stores
        const int v0 = vt * 128;
        const int rbase = b0 + warp_m * 64 + (lid >> 2);
        const int cbase = v0 + warp_n * 32 + (lid & 3) * 2;
        #pragma unroll
        for (int mf = 0; mf < 4; mf++) {
            #pragma unroll
            for (int nf = 0; nf < 4; nf++) {
                int col = cbase + nf * 8;
                float* r0p = out + (size_t)(rbase + mf * 16) * VOUT;
                float* r1p = r0p + (size_t)8 * VOUT;
                if (col < VOUT) {
                    r0p[col] = c[mf][nf][0]; r1p[col] = c[mf][nf][2];
                }
                if (col + 1 < VOUT) {
                    r0p[col + 1] = c[mf][nf][1]; r1p[col + 1] = c[mf][nf][3];
                }
            }
        }
        __syncthreads();   // buffer (t&1) free for prefetch of t+2
    }
}

// ===========================================================================
extern "C" void kernel_launch(void* const* d_in, const int* in_sizes, int n_in,
                              void* d_out, int out_size)
{
    const int*   alias_inputs = (const int*)  d_in[0];
    const float* ain   = (const float*)d_in[1];
    const float* aou   = (const float*)d_in[2];
    const int*   items = (const int*)  d_in[3];
    const int*   mask  = (const int*)  d_in[4];
    /* d_in[5] edge_index unused */
    const float* emb   = (const float*)d_in[6];
    const float* einw  = (const float*)d_in[7];
    const float* einb  = (const float*)d_in[8];
    const float* eouw  = (const float*)d_in[9];
    const float* eoub  = (const float*)d_in[10];
    const float* biah  = (const float*)d_in[11];
    const float* boah  = (const float*)d_in[12];
    const float* igw   = (const float*)d_in[13];
    const float* igb   = (const float*)d_in[14];
    const float* hgw   = (const float*)d_in[15];
    const float* hgb   = (const float*)d_in[16];
    const float* fc1w  = (const float*)d_in[17];
    const float* fc1b  = (const float*)d_in[18];
    const float* fc2w  = (const float*)d_in[19];
    const float* fc2b  = (const float*)d_in[20];
    const float* fc3w  = (const float*)d_in[21];
    float* out = (float*)d_out;

    cudaFuncSetAttribute(session_kernel,
                         cudaFuncAttributeMaxDynamicSharedMemorySize,
                         SM1_FLOATS * 4);
    cudaFuncSetAttribute(gemm_mma_kernel,
                         cudaFuncAttributeMaxDynamicSharedMemorySize,
                         GT_BYTES);

    split_kernel<<<(VOCAB * 16 + 255) / 256, 256>>>(emb);

    session_kernel<<<BATCH, 256, SM1_FLOATS * 4>>>(
        alias_inputs, ain, aou, items, mask, emb,
        einw, einb, eouw, eoub, biah, boah,
        igw, igb, hgw, hgb, fc1w, fc1b, fc2w, fc2b, fc3w);

    dim3 grid(8, (NVTILES + T_VTILES - 1) / T_VTILES, 1);
    gemm_mma_kernel<<<grid, 256, GT_BYTES>>>(out);
}